// round 8
// baseline (speedup 1.0000x reference)
#include <cuda_runtime.h>
#include <cuda_bf16.h>
#include <cstddef>

// Problem constants (fixed by reference: L=16, KV=4, V=2, B=512)
#define S_  65536
#define R_  4096
#define D_  16
#define B_  512
#define PS_ (B_ * R_)           // 2097152
#define NC_ ((size_t)B_ * S_)   // 33554432

// Block = 256 threads = 1/8 of a batch row (512 r, 8192 s). Each thread owns
// TWO r's (float2 path) — half the register state of the float4 version, so
// ~7-8 blocks/SM instead of 5 (the R7 kernel was occupancy-capped at 47 regs,
// DRAM stuck at 64% with nothing saturated => latency/concurrency bound).
// Warps stay fully decoupled: phase 2 of warp w reads only bvf[w*64..+64)
// which warp w itself wrote in phase 1 (__syncwarp only, no block barrier).
// prev_state is pure ALU: state_candidates[r,d] = r + (d<<12) by construction.
__global__ __launch_bounds__(256, 7)
void trellis_fused_kernel(const float*  __restrict__ lut,   // [S,2]
                          const float*  __restrict__ cost,  // [B,S]
                          const float*  __restrict__ orig,  // [B,2]
                          float*        __restrict__ ps_out,
                          float*        __restrict__ nc_out)
{
    __shared__ float bvf[512];      // best_val, local r; warp w owns [w*64,+64)

    const int tid  = threadIdx.x;
    const int lane = tid & 31;
    const int w    = tid >> 5;                  // warp id 0..7
    const int b    = blockIdx.x >> 3;           // 8 blocks per batch row
    const int o    = blockIdx.x & 7;            // octant of the row
    const int rh   = (o << 8) + tid;            // global r-half index (r/2) in [0,2048)

    const float2* __restrict__ cbh = (const float2*)(cost + (size_t)b * S_);

    // ---- Phase 1: min/argmin over d for r = 2*rh, 2*rh+1
    //      (strict '<' => first occurrence, matching jnp.argmin)
    float2 best = __ldcs(&cbh[rh]);
    int bd0 = 0, bd1 = 0;
    #pragma unroll
    for (int d = 1; d < D_; ++d) {
        float2 v = __ldcs(&cbh[d * (R_ / 2) + rh]);
        if (v.x < best.x) { best.x = v.x; bd0 = d; }
        if (v.y < best.y) { best.y = v.y; bd1 = d; }
    }

    ((float2*)bvf)[tid] = best;     // bvf[2*tid], bvf[2*tid+1]

    // prev_state[b,r] = sc[r,best_idx] = r + (best_idx << 12)  (pure ALU)
    if (ps_out) {
        const int r0 = rh << 1;
        float2 ps;
        ps.x = (float)(r0 + 0 + (bd0 << 12));
        ps.y = (float)(r0 + 1 + (bd1 << 12));
        __stcs(&((float2*)ps_out)[(size_t)b * (R_ / 2) + rh], ps);
    }

    __syncwarp();   // phase 2 reads only this warp's own bvf slice

    // ---- Phase 2: coalesced new_cost epilogue (warp-independent)
    if (nc_out) {
        const float o0 = __ldg(&orig[2 * b + 0]);
        const float o1 = __ldg(&orig[2 * b + 1]);

        const float4* __restrict__ lvf4 = (const float4*)lut;  // f4 j = states 2j,2j+1
        float2* __restrict__ nc2 = (float2*)(nc_out + (size_t)b * S_);

        const int hb = o * 4096 + w * 512;   // warp's f4/f2 index base

        #pragma unroll
        for (int it = 0; it < 16; ++it) {
            const int jb = hb + it * 32;             // 32 lut f4s = 64 states
            const float4 A = __ldg(&lvf4[jb + lane]);

            // local r for this f4: (jb+lane)>>3 - o*512 = w*64 + it*4 + (lane>>3)
            const float bv = bvf[w * 64 + it * 4 + (lane >> 3)];

            float dx, dy;
            float2 oA;
            dx = A.x - o0; dy = A.y - o1; oA.x = fmaf(dx, dx, dy * dy) + bv;
            dx = A.z - o0; dy = A.w - o1; oA.y = fmaf(dx, dx, dy * dy) + bv;

            __stcs(&nc2[jb + lane], oA);
        }
    }
}

extern "C" void kernel_launch(void* const* d_in, const int* in_sizes, int n_in,
                              void* d_out, int out_size)
{
    const float* lut  = (const float*)d_in[0];
    const float* cost = (const float*)d_in[1];
    const float* orig = (const float*)d_in[2];
    float* out = (float*)d_out;

    float* ps_out = nullptr;
    float* nc_out = nullptr;
    const size_t osz = (size_t)out_size;
    if (osz >= (size_t)PS_ + NC_) {
        ps_out = out;
        nc_out = out + PS_;
    } else if (osz == NC_) {
        nc_out = out;
    } else {
        ps_out = out;
    }

    trellis_fused_kernel<<<B_ * 8, 256>>>(lut, cost, orig, ps_out, nc_out);
}